// round 12
// baseline (speedup 1.0000x reference)
#include <cuda_runtime.h>
#include <cuda_fp16.h>
#include <math.h>

#define PI_F 3.14159265358979323846f
#define MARGIN_F 9.0f

#define DIM 512
#define HALF 256
#define NUM_REL 64
#define MAX_NODES 100000
#define MAX_EDGES 1048576
#define ROT_BLOCKS 64

// Chunk-interleaved fp16 node table: row = 32 chunks of 32B;
// chunk k = re[8k..8k+8) ++ im[8k..8k+8).  100000 x 1KB = 102.4 MB.
__device__ __half g_nodesP[(size_t)MAX_NODES * DIM];

// Fused rot table: per relation 32 chunks; chunk k = cos8 ++ sin8. 64 KB.
__device__ __half g_rotP[NUM_REL * DIM];

__device__ float g_scale;
__device__ float g_bias;

// Counting-sort scratch (sort edges by exact head id).
__device__ int  g_cnt[MAX_NODES];
__device__ int  g_off[MAX_NODES];
__device__ int4 g_perm[MAX_EDGES];   // (head, tail, rel, orig_idx)

// ---- policy + hinted memory ops ----
__device__ __forceinline__ unsigned long long mk_evict_last_policy() {
    unsigned long long p;
    asm("createpolicy.fractional.L2::evict_last.b64 %0, 1.0;" : "=l"(p));
    return p;
}
__device__ __forceinline__ void ldg256_hint(const void* p, unsigned long long pol,
                                            uint4& a, uint4& b) {
    asm("ld.global.L2::cache_hint.v8.b32 {%0,%1,%2,%3,%4,%5,%6,%7}, [%8], %9;"
        : "=r"(a.x), "=r"(a.y), "=r"(a.z), "=r"(a.w),
          "=r"(b.x), "=r"(b.y), "=r"(b.z), "=r"(b.w)
        : "l"(p), "l"(pol));
}
__device__ __forceinline__ void stg256_hint(void* p, unsigned long long pol,
                                            uint4 a, uint4 b) {
    asm volatile("st.global.L2::cache_hint.v8.b32 [%0], {%1,%2,%3,%4,%5,%6,%7,%8}, %9;"
        :: "l"(p), "r"(a.x), "r"(a.y), "r"(a.z), "r"(a.w),
           "r"(b.x), "r"(b.y), "r"(b.z), "r"(b.w), "l"(pol) : "memory");
}
__device__ __forceinline__ float4 ldg_streaming_f4(const float4* p) {
    float4 v;
    asm("ld.global.cs.v4.f32 {%0,%1,%2,%3}, [%4];"
        : "=f"(v.x), "=f"(v.y), "=f"(v.z), "=f"(v.w) : "l"(p));
    return v;
}
__device__ __forceinline__ float sqrt_approx(float x) {
    float r;
    asm("sqrt.approx.f32 %0, %1;" : "=f"(r) : "f"(x));
    return r;
}
__device__ __forceinline__ unsigned pack2(float lo, float hi) {
    __half2 h = __floats2half2_rn(lo, hi);
    return *(unsigned*)&h;
}

// Fused prep: rot tables + epilogue constants | zero counters | fp32->fp16
// chunk-interleaved node conversion.
__global__ void __launch_bounds__(256)
prep_kernel(const float* __restrict__ relation_emb,
            const float* __restrict__ nodes,
            const float* __restrict__ temperature,
            const float* __restrict__ bias,
            long long n_chunks, int num_nodes, int zero_blocks) {
    if (blockIdx.x < ROT_BLOCKS) {
        int i = blockIdx.x * blockDim.x + threadIdx.x;
        if (i == 0) {
            g_scale = -1.0f / ((float)HALF * temperature[0]);
            g_bias  = bias[0];
        }
        if (i < NUM_REL * HALF) {
            int r = i >> 8;
            int j = i & 255;
            float phase = relation_emb[i] * (PI_F / MARGIN_F);
            float s, c;
            sincosf(phase, &s, &c);
            int base = r * DIM + (j >> 3) * 16 + (j & 7);
            g_rotP[base]     = __float2half_rn(c);
            g_rotP[base + 8] = __float2half_rn(s);
        }
        return;
    }
    if (blockIdx.x < ROT_BLOCKS + zero_blocks) {
        int i = (blockIdx.x - ROT_BLOCKS) * blockDim.x + threadIdx.x;
        if (i < num_nodes) g_cnt[i] = 0;
        return;
    }
    long long i = (long long)(blockIdx.x - ROT_BLOCKS - zero_blocks) * blockDim.x
                  + threadIdx.x;
    if (i >= n_chunks) return;
    long long node = i >> 5;
    int k = (int)(i & 31);
    const float4* src = (const float4*)(nodes + node * DIM);
    float4 r0 = ldg_streaming_f4(&src[2 * k]);
    float4 r1 = ldg_streaming_f4(&src[2 * k + 1]);
    float4 i0 = ldg_streaming_f4(&src[64 + 2 * k]);
    float4 i1 = ldg_streaming_f4(&src[64 + 2 * k + 1]);
    uint4 a, b;
    a.x = pack2(r0.x, r0.y); a.y = pack2(r0.z, r0.w);
    a.z = pack2(r1.x, r1.y); a.w = pack2(r1.z, r1.w);
    b.x = pack2(i0.x, i0.y); b.y = pack2(i0.z, i0.w);
    b.z = pack2(i1.x, i1.y); b.w = pack2(i1.z, i1.w);
    unsigned long long pol = mk_evict_last_policy();
    stg256_hint((char*)g_nodesP + i * 32, pol, a, b);
}

// Histogram of head ids. ~10 edges/node -> negligible atomic contention.
__global__ void __launch_bounds__(256)
hist_kernel(const int* __restrict__ edge_index, int num_edges) {
    int e = blockIdx.x * blockDim.x + threadIdx.x;
    if (e < num_edges) atomicAdd(&g_cnt[edge_index[e]], 1);
}

// Exclusive scan over num_nodes counters: one block, 1024 threads,
// serial chunk per thread + block scan of totals.
__global__ void __launch_bounds__(1024)
scan_kernel(int num_nodes) {
    __shared__ int sums[1024];
    int t = threadIdx.x;
    int chunk = (num_nodes + 1023) / 1024;
    int lo = t * chunk;
    int hi = min(lo + chunk, num_nodes);
    int s = 0;
    for (int i = lo; i < hi; i++) s += g_cnt[i];
    sums[t] = s;
    __syncthreads();
    #pragma unroll
    for (int off = 1; off < 1024; off <<= 1) {
        int v = (t >= off) ? sums[t - off] : 0;
        __syncthreads();
        sums[t] += v;
        __syncthreads();
    }
    int base = (t == 0) ? 0 : sums[t - 1];
    for (int i = lo; i < hi; i++) {
        int c = g_cnt[i];
        g_off[i] = base;
        base += c;
    }
}

// Scatter edges into head-sorted order.
__global__ void __launch_bounds__(256)
scatter_kernel(const int* __restrict__ edge_index,
               const int* __restrict__ rel_type, int num_edges) {
    int e = blockIdx.x * blockDim.x + threadIdx.x;
    if (e >= num_edges) return;
    int h = edge_index[e];
    int p = atomicAdd(&g_off[h], 1);
    g_perm[p] = make_int4(h, edge_index[num_edges + e], rel_type[e], e);
}

// One edge's partial distance sum for this lane: 3 x 256-bit loads.
// Heads of consecutive edges repeat (sorted) -> L1 hits after first touch.
__device__ __forceinline__ float edge_partial(long long h, long long t, int r,
                                              int laneB, unsigned long long pol) {
    uint4 reh, imh, ret, imt, crr, srr;
    ldg256_hint((const char*)g_nodesP + (h << 10) + laneB, pol, reh, imh);
    ldg256_hint((const char*)g_nodesP + (t << 10) + laneB, pol, ret, imt);
    ldg256_hint((const char*)g_rotP + ((long long)r << 10) + laneB, pol, crr, srr);

    const unsigned* rh_w = &reh.x;
    const unsigned* ih_w = &imh.x;
    const unsigned* rt_w = &ret.x;
    const unsigned* it_w = &imt.x;
    const unsigned* cr_w = &crr.x;
    const unsigned* sr_w = &srr.x;

    float a0 = 0.0f, a1 = 0.0f;
    #pragma unroll
    for (int w = 0; w < 4; w++) {
        __half2 rh2 = *(const __half2*)&rh_w[w];
        __half2 ih2 = *(const __half2*)&ih_w[w];
        __half2 rt2 = *(const __half2*)&rt_w[w];
        __half2 it2 = *(const __half2*)&it_w[w];
        __half2 cr2 = *(const __half2*)&cr_w[w];
        __half2 sr2 = *(const __half2*)&sr_w[w];

        __half2 wv  = __hfma2(ih2, sr2, rt2);
        __half2 re2 = __hfma2(rh2, cr2, __hneg2(wv));
        __half2 im2 = __hfma2(rh2, sr2, __hfma2(ih2, cr2, __hneg2(it2)));
        __half2 d2  = __hfma2(re2, re2, __hmul2(im2, im2));

        float2 d = __half22float2(d2);
        a0 += sqrt_approx(d.x);
        a1 += sqrt_approx(d.y);
    }
    return a0 + a1;
}

// Two (head-sorted) edges per warp; paired butterfly reduction.
__global__ void __launch_bounds__(256)
rotate_score_kernel(float* __restrict__ out, int num_edges) {
    int wp = (blockIdx.x * blockDim.x + threadIdx.x) >> 5;
    int lane = threadIdx.x & 31;
    int e0 = wp * 2;
    if (e0 >= num_edges) return;
    bool hasB = (e0 + 1) < num_edges;

    int4 A = g_perm[e0];
    int4 B = hasB ? g_perm[e0 + 1] : A;

    unsigned long long pol = mk_evict_last_policy();
    int laneB = lane * 32;

    float sA = edge_partial((long long)A.x, (long long)A.y, A.z, laneB, pol);
    float sB = edge_partial((long long)B.x, (long long)B.y, B.z, laneB, pol);

    bool hi = (lane & 16) != 0;
    float send = hi ? sA : sB;
    float keep = hi ? sB : sA;
    float v = keep + __shfl_xor_sync(0xffffffffu, send, 16);
    #pragma unroll
    for (int off = 8; off > 0; off >>= 1)
        v += __shfl_xor_sync(0xffffffffu, v, off);

    float res = fmaf(v, g_scale, g_bias);
    if (lane == 0) out[A.w] = res;
    if (lane == 16 && hasB) out[B.w] = res;
}

extern "C" void kernel_launch(void* const* d_in, const int* in_sizes, int n_in,
                              void* d_out, int out_size) {
    const float* nodes       = (const float*)d_in[0];
    const int*   edge_index  = (const int*)d_in[1];
    const int*   rel_type    = (const int*)d_in[2];
    const float* rel_emb     = (const float*)d_in[3];
    const float* temperature = (const float*)d_in[4];
    const float* bias        = (const float*)d_in[5];
    float*       out         = (float*)d_out;

    int num_edges = in_sizes[2];
    int num_nodes = in_sizes[0] / DIM;
    long long n_chunks = (long long)in_sizes[0] / 16;

    int zero_blocks = (num_nodes + 255) / 256;
    int conv_blocks = (int)((n_chunks + 255) / 256);
    prep_kernel<<<ROT_BLOCKS + zero_blocks + conv_blocks, 256>>>(
        rel_emb, nodes, temperature, bias, n_chunks, num_nodes, zero_blocks);

    hist_kernel<<<(num_edges + 255) / 256, 256>>>(edge_index, num_edges);
    scan_kernel<<<1, 1024>>>(num_nodes);
    scatter_kernel<<<(num_edges + 255) / 256, 256>>>(edge_index, rel_type,
                                                     num_edges);

    int pairs = (num_edges + 1) / 2;
    int warps_per_block = 256 / 32;
    int blocks = (pairs + warps_per_block - 1) / warps_per_block;
    rotate_score_kernel<<<blocks, 256>>>(out, num_edges);
}

// round 13
// speedup vs baseline: 1.6446x; 1.6446x over previous
#include <cuda_runtime.h>
#include <cuda_fp16.h>
#include <math.h>

#define PI_F 3.14159265358979323846f
#define MARGIN_F 9.0f

#define DIM 512
#define HALF 256
#define NUM_REL 64
#define MAX_NODES 100000
#define ROT_BLOCKS 64

// Chunk-interleaved fp16 node table: row = 32 chunks of 32B;
// chunk k = re[8k..8k+8) ++ im[8k..8k+8).  100000 x 1KB = 102.4 MB.
__device__ __half g_nodesP[(size_t)MAX_NODES * DIM];

// Fused rot table: per relation 32 chunks; chunk k = cos8 ++ sin8. 64 KB.
__device__ __half g_rotP[NUM_REL * DIM];

__device__ float g_scale;
__device__ float g_bias;

// ---- policy + hinted memory ops ----
__device__ __forceinline__ unsigned long long mk_evict_last_policy() {
    unsigned long long p;
    asm("createpolicy.fractional.L2::evict_last.b64 %0, 1.0;" : "=l"(p));
    return p;
}
__device__ __forceinline__ void ldg256_hint(const void* p, unsigned long long pol,
                                            uint4& a, uint4& b) {
    asm("ld.global.L2::cache_hint.v8.b32 {%0,%1,%2,%3,%4,%5,%6,%7}, [%8], %9;"
        : "=r"(a.x), "=r"(a.y), "=r"(a.z), "=r"(a.w),
          "=r"(b.x), "=r"(b.y), "=r"(b.z), "=r"(b.w)
        : "l"(p), "l"(pol));
}
__device__ __forceinline__ void stg256_hint(void* p, unsigned long long pol,
                                            uint4 a, uint4 b) {
    asm volatile("st.global.L2::cache_hint.v8.b32 [%0], {%1,%2,%3,%4,%5,%6,%7,%8}, %9;"
        :: "l"(p), "r"(a.x), "r"(a.y), "r"(a.z), "r"(a.w),
           "r"(b.x), "r"(b.y), "r"(b.z), "r"(b.w), "l"(pol) : "memory");
}
__device__ __forceinline__ float4 ldg_streaming_f4(const float4* p) {
    float4 v;
    asm("ld.global.cs.v4.f32 {%0,%1,%2,%3}, [%4];"
        : "=f"(v.x), "=f"(v.y), "=f"(v.z), "=f"(v.w) : "l"(p));
    return v;
}
__device__ __forceinline__ int2 ldg_streaming_i2(const int2* p) {
    int2 v;
    asm("ld.global.cs.v2.u32 {%0,%1}, [%2];" : "=r"(v.x), "=r"(v.y) : "l"(p));
    return v;
}
__device__ __forceinline__ int ldg_streaming_i(const int* p) {
    int v;
    asm("ld.global.cs.u32 %0, [%1];" : "=r"(v) : "l"(p));
    return v;
}
__device__ __forceinline__ void stg_streaming_f(float* p, float v) {
    asm volatile("st.global.cs.f32 [%0], %1;" :: "l"(p), "f"(v) : "memory");
}
__device__ __forceinline__ float sqrt_approx(float x) {
    float r;
    asm("sqrt.approx.f32 %0, %1;" : "=f"(r) : "f"(x));
    return r;
}
__device__ __forceinline__ unsigned pack2(float lo, float hi) {
    __half2 h = __floats2half2_rn(lo, hi);
    return *(unsigned*)&h;
}

// Fused prep: rot tables + epilogue constants | fp32->fp16 chunk-interleaved
// node conversion (source streamed evict-first, table stored evict-last).
__global__ void __launch_bounds__(256)
prep_kernel(const float* __restrict__ relation_emb,
            const float* __restrict__ nodes,
            const float* __restrict__ temperature,
            const float* __restrict__ bias,
            long long n_chunks) {
    if (blockIdx.x < ROT_BLOCKS) {
        int i = blockIdx.x * blockDim.x + threadIdx.x;
        if (i == 0) {
            g_scale = -1.0f / ((float)HALF * temperature[0]);
            g_bias  = bias[0];
        }
        if (i < NUM_REL * HALF) {
            int r = i >> 8;
            int j = i & 255;
            float phase = relation_emb[i] * (PI_F / MARGIN_F);
            float s, c;
            sincosf(phase, &s, &c);
            int base = r * DIM + (j >> 3) * 16 + (j & 7);
            g_rotP[base]     = __float2half_rn(c);
            g_rotP[base + 8] = __float2half_rn(s);
        }
        return;
    }
    long long i = (long long)(blockIdx.x - ROT_BLOCKS) * blockDim.x + threadIdx.x;
    if (i >= n_chunks) return;
    long long node = i >> 5;
    int k = (int)(i & 31);
    const float4* src = (const float4*)(nodes + node * DIM);
    float4 r0 = ldg_streaming_f4(&src[2 * k]);
    float4 r1 = ldg_streaming_f4(&src[2 * k + 1]);
    float4 i0 = ldg_streaming_f4(&src[64 + 2 * k]);
    float4 i1 = ldg_streaming_f4(&src[64 + 2 * k + 1]);
    uint4 a, b;
    a.x = pack2(r0.x, r0.y); a.y = pack2(r0.z, r0.w);
    a.z = pack2(r1.x, r1.y); a.w = pack2(r1.z, r1.w);
    b.x = pack2(i0.x, i0.y); b.y = pack2(i0.z, i0.w);
    b.z = pack2(i1.x, i1.y); b.w = pack2(i1.z, i1.w);
    unsigned long long pol = mk_evict_last_policy();
    stg256_hint((char*)g_nodesP + i * 32, pol, a, b);
}

// One edge's partial distance sum for this lane: 3 x 256-bit loads.
__device__ __forceinline__ float edge_partial(long long h, long long t, int r,
                                              int laneB, unsigned long long pol) {
    uint4 reh, imh, ret, imt, crr, srr;
    ldg256_hint((const char*)g_nodesP + (h << 10) + laneB, pol, reh, imh);
    ldg256_hint((const char*)g_nodesP + (t << 10) + laneB, pol, ret, imt);
    ldg256_hint((const char*)g_rotP + ((long long)r << 10) + laneB, pol, crr, srr);

    const unsigned* rh_w = &reh.x;
    const unsigned* ih_w = &imh.x;
    const unsigned* rt_w = &ret.x;
    const unsigned* it_w = &imt.x;
    const unsigned* cr_w = &crr.x;
    const unsigned* sr_w = &srr.x;

    float a0 = 0.0f, a1 = 0.0f;
    #pragma unroll
    for (int w = 0; w < 4; w++) {
        __half2 rh2 = *(const __half2*)&rh_w[w];
        __half2 ih2 = *(const __half2*)&ih_w[w];
        __half2 rt2 = *(const __half2*)&rt_w[w];
        __half2 it2 = *(const __half2*)&it_w[w];
        __half2 cr2 = *(const __half2*)&cr_w[w];
        __half2 sr2 = *(const __half2*)&sr_w[w];

        __half2 wv  = __hfma2(ih2, sr2, rt2);
        __half2 re2 = __hfma2(rh2, cr2, __hneg2(wv));
        __half2 im2 = __hfma2(rh2, sr2, __hfma2(ih2, cr2, __hneg2(it2)));
        __half2 d2  = __hfma2(re2, re2, __hmul2(im2, im2));

        float2 d = __half22float2(d2);
        a0 += sqrt_approx(d.x);
        a1 += sqrt_approx(d.y);
    }
    return a0 + a1;
}

// Four edges per warp (two pair-iterations). Edge/out streams are .cs so the
// only evict-last data competing for L2 is the node table.
__global__ void __launch_bounds__(256)
rotate_score_kernel(const int* __restrict__ edge_index,
                    const int* __restrict__ rel_type,
                    float* __restrict__ out,
                    int num_edges) {
    int gw = (blockIdx.x * blockDim.x + threadIdx.x) >> 5;
    int lane = threadIdx.x & 31;
    int npairs = (num_edges + 1) >> 1;

    unsigned long long pol = mk_evict_last_policy();
    int laneB = lane * 32;
    bool hi = (lane & 16) != 0;
    float scale = g_scale;
    float bval  = g_bias;

    #pragma unroll
    for (int it = 0; it < 2; it++) {
        int wp = gw * 2 + it;
        if (wp >= npairs) return;
        int e0 = wp * 2;
        bool hasB = (e0 + 1) < num_edges;

        int hA, hB, tA, tB, rA, rB;
        if (hasB) {
            int2 hh = ldg_streaming_i2(((const int2*)edge_index) + wp);
            int2 tt = ldg_streaming_i2(((const int2*)(edge_index + num_edges)) + wp);
            int2 rr = ldg_streaming_i2(((const int2*)rel_type) + wp);
            hA = hh.x; hB = hh.y; tA = tt.x; tB = tt.y; rA = rr.x; rB = rr.y;
        } else {
            hA = ldg_streaming_i(edge_index + e0);
            tA = ldg_streaming_i(edge_index + num_edges + e0);
            rA = ldg_streaming_i(rel_type + e0);
            hB = hA; tB = tA; rB = rA;
        }

        float sA = edge_partial((long long)hA, (long long)tA, rA, laneB, pol);
        float sB = edge_partial((long long)hB, (long long)tB, rB, laneB, pol);

        // Pair-combine: lanes 0-15 accumulate edge A, lanes 16-31 edge B.
        float send = hi ? sA : sB;
        float keep = hi ? sB : sA;
        float v = keep + __shfl_xor_sync(0xffffffffu, send, 16);
        #pragma unroll
        for (int off = 8; off > 0; off >>= 1)
            v += __shfl_xor_sync(0xffffffffu, v, off);

        float res = fmaf(v, scale, bval);
        if (lane == 0) stg_streaming_f(out + e0, res);
        if (lane == 16 && hasB) stg_streaming_f(out + e0 + 1, res);
    }
}

extern "C" void kernel_launch(void* const* d_in, const int* in_sizes, int n_in,
                              void* d_out, int out_size) {
    const float* nodes       = (const float*)d_in[0];
    const int*   edge_index  = (const int*)d_in[1];
    const int*   rel_type    = (const int*)d_in[2];
    const float* rel_emb     = (const float*)d_in[3];
    const float* temperature = (const float*)d_in[4];
    const float* bias        = (const float*)d_in[5];
    float*       out         = (float*)d_out;

    int num_edges = in_sizes[2];
    long long n_chunks = (long long)in_sizes[0] / 16;

    int conv_blocks = (int)((n_chunks + 255) / 256);
    prep_kernel<<<ROT_BLOCKS + conv_blocks, 256>>>(rel_emb, nodes,
                                                   temperature, bias, n_chunks);

    // 4 edges per warp, 8 warps per block -> 32 edges per block.
    int blocks = (num_edges + 31) / 32;
    rotate_score_kernel<<<blocks, 256>>>(edge_index, rel_type, out, num_edges);
}